// round 4
// baseline (speedup 1.0000x reference)
#include <cuda_runtime.h>
#include <cuda_bf16.h>
#include <math.h>
#include <stdint.h>

// Problem constants
#define BN    256
#define TT    64
#define VOC   10000
#define VISD  1024
#define WORDD 512
#define RNN   512
#define G4    2048
#define NG    2560          // 2048 lstm gates + 512 sentinel gate
#define NL    10001
#define NLP   10112         // padded rows for outWT (zero-filled)
#define NPB   157           // 64-col tiles covering [0, 10048) >= NL
#define MW    (TT*BN)       // 16384

// ---------------- device scratch ----------------
__device__ __nv_bfloat16 g_visA[BN*VISD];
__device__ __nv_bfloat16 g_WvisT[NG*VISD];
__device__ float         g_biasvis[NG];
__device__ float         g_visgates[BN*NG];
__device__ __nv_bfloat16 g_wordsA[MW*WORDD];
__device__ __nv_bfloat16 g_WwT[NG*WORDD];
__device__ float         g_wordgates[MW*NG];        // includes visgates+biases
__device__ __nv_bfloat16 g_WhhT[NG*RNN];
__device__ __nv_bfloat16 g_outWT[NLP*RNN];
__device__ float         g_bias_out[NLP];
__device__ float         g_hgates[BN*NG];
__device__ float         g_c[BN*RNN];
__device__ __nv_bfloat16 g_h[BN*RNN];
__device__ __nv_bfloat16 g_s[BN*RNN];
__device__ float2        g_part[NPB*BN];
__device__ float         g_tgtval[BN];

// ---------------- helpers ----------------
__device__ __forceinline__ uint32_t s2u(const void* p) {
    return (uint32_t)__cvta_generic_to_shared(p);
}
__device__ __forceinline__ void ldsm4(uint32_t r[4], uint32_t addr) {
    asm volatile("ldmatrix.sync.aligned.m8n8.x4.shared.b16 {%0,%1,%2,%3}, [%4];"
                 : "=r"(r[0]), "=r"(r[1]), "=r"(r[2]), "=r"(r[3]) : "r"(addr));
}
__device__ __forceinline__ void mma16816(float c[4], const uint32_t a[4],
                                         uint32_t b0, uint32_t b1) {
    asm volatile(
        "mma.sync.aligned.m16n8k16.row.col.f32.bf16.bf16.f32 "
        "{%0,%1,%2,%3}, {%4,%5,%6,%7}, {%8,%9}, {%0,%1,%2,%3};"
        : "+f"(c[0]), "+f"(c[1]), "+f"(c[2]), "+f"(c[3])
        : "r"(a[0]), "r"(a[1]), "r"(a[2]), "r"(a[3]), "r"(b0), "r"(b1));
}
__device__ __forceinline__ float sigf(float x) { return 1.f / (1.f + expf(-x)); }

// ---------------- prep kernels ----------------
__global__ void k_cvt_vis(const float* __restrict__ vis) {
    int i = blockIdx.x * 256 + threadIdx.x;
    g_visA[i] = __float2bfloat16(vis[i]);
}

__global__ void k_transpose_cvt(const float* __restrict__ src, int sld, int K, int N,
                                __nv_bfloat16* __restrict__ dst, int dld, int Ndst) {
    __shared__ float tile[32][33];
    int nb = blockIdx.x * 32, kb = blockIdx.y * 32;
    int tx = threadIdx.x, ty = threadIdx.y;
    #pragma unroll
    for (int i = ty; i < 32; i += 8) {
        int k = kb + i, n = nb + tx;
        tile[i][tx] = (k < K && n < N) ? src[(size_t)k * sld + n] : 0.f;
    }
    __syncthreads();
    #pragma unroll
    for (int i = ty; i < 32; i += 8) {
        int n = nb + i, k = kb + tx;
        if (n < Ndst) dst[(size_t)n * dld + k] = __float2bfloat16(tile[tx][i]);
    }
}

__global__ void k_bias(const float* __restrict__ bl, const float* __restrict__ vb,
                       const float* __restrict__ ob) {
    int i = blockIdx.x * 256 + threadIdx.x;
    if (i < NG)  g_biasvis[i] = (i < G4) ? bl[i] : vb[i - G4];
    if (i < NLP) g_bias_out[i] = (i < NL) ? ob[i] : 0.f;
}

__global__ void k_wordsA(const float* __restrict__ emb, const int* __restrict__ seqz) {
    int idx = blockIdx.x * 256 + threadIdx.x;
    int r = idx >> 9, k = idx & 511;
    int t = r >> 8, b = r & 255;
    int widx = (t == 0) ? (VOC + 1) : seqz[b * TT + (t - 1)];
    g_wordsA[idx] = __float2bfloat16(emb[(size_t)widx * WORDD + k]);
}

__global__ void k_init() {
    int i = blockIdx.x * 256 + threadIdx.x;
    g_h[i] = __float2bfloat16(0.f);
    g_c[i] = 0.f;
}

// ---------------- 64x64 MMA GEMM core (proven fast shape) ----------------
// Computes acc for tile (m0, n0); 4 warps, warp tile 32x32.
__device__ __forceinline__ void gemm64_core(const __nv_bfloat16* __restrict__ A,
                                            const __nv_bfloat16* __restrict__ Bm,
                                            int K, int m0, int n0,
                                            __nv_bfloat16 (*As)[64][40],
                                            __nv_bfloat16 (*Bs)[64][40],
                                            float acc[2][4][4]) {
    const int tid  = threadIdx.x;
    const int lane = tid & 31;
    const int warp = tid >> 5;
    const int wm = (warp >> 1) * 32;
    const int wn = (warp & 1) * 32;
    const int lr = tid >> 2;
    const int lc = (tid & 3) * 8;

    const __nv_bfloat16* Ag0 = A  + (size_t)(m0 + lr)      * K + lc;
    const __nv_bfloat16* Ag1 = A  + (size_t)(m0 + lr + 32) * K + lc;
    const __nv_bfloat16* Bg0 = Bm + (size_t)(n0 + lr)      * K + lc;
    const __nv_bfloat16* Bg1 = Bm + (size_t)(n0 + lr + 32) * K + lc;

    uint4 ra0 = *(const uint4*)Ag0;
    uint4 ra1 = *(const uint4*)Ag1;
    uint4 rb0 = *(const uint4*)Bg0;
    uint4 rb1 = *(const uint4*)Bg1;

    *(uint4*)(&As[0][lr][lc])      = ra0;
    *(uint4*)(&As[0][lr + 32][lc]) = ra1;
    *(uint4*)(&Bs[0][lr][lc])      = rb0;
    *(uint4*)(&Bs[0][lr + 32][lc]) = rb1;
    __syncthreads();

    const int KT = K >> 5;
    for (int kt = 0; kt < KT; ++kt) {
        const int cur = kt & 1;
        if (kt + 1 < KT) {
            const int kb = (kt + 1) << 5;
            ra0 = *(const uint4*)(Ag0 + kb);
            ra1 = *(const uint4*)(Ag1 + kb);
            rb0 = *(const uint4*)(Bg0 + kb);
            rb1 = *(const uint4*)(Bg1 + kb);
        }
        #pragma unroll
        for (int ks = 0; ks < 2; ++ks) {
            uint32_t af[2][4], bfq[2][4];
            #pragma unroll
            for (int mt = 0; mt < 2; ++mt)
                ldsm4(af[mt], s2u(&As[cur][wm + mt * 16 + (lane & 15)]
                                          [ks * 16 + (lane >> 4) * 8]));
            #pragma unroll
            for (int np = 0; np < 2; ++np)
                ldsm4(bfq[np], s2u(&Bs[cur][wn + np * 16 + (lane & 7) + ((lane >> 4) & 1) * 8]
                                           [ks * 16 + ((lane >> 3) & 1) * 8]));
            #pragma unroll
            for (int mt = 0; mt < 2; ++mt)
                #pragma unroll
                for (int nt = 0; nt < 4; ++nt)
                    mma16816(acc[mt][nt], af[mt],
                             bfq[nt >> 1][(nt & 1) * 2], bfq[nt >> 1][(nt & 1) * 2 + 1]);
        }
        if (kt + 1 < KT) {
            const int nxt = cur ^ 1;
            *(uint4*)(&As[nxt][lr][lc])      = ra0;
            *(uint4*)(&As[nxt][lr + 32][lc]) = ra1;
            *(uint4*)(&Bs[nxt][lr][lc])      = rb0;
            *(uint4*)(&Bs[nxt][lr + 32][lc]) = rb1;
        }
        __syncthreads();
    }
}

// C = A @ B^T (+bias[n]) (+addv[r%256][c])
__global__ void __launch_bounds__(128)
k_gemm(const __nv_bfloat16* __restrict__ A, const __nv_bfloat16* __restrict__ Bm,
       float* __restrict__ C, int M, int N, int K,
       const float* __restrict__ bias, const float* __restrict__ addv) {
    __shared__ __align__(16) __nv_bfloat16 As[2][64][40];
    __shared__ __align__(16) __nv_bfloat16 Bs[2][64][40];
    float acc[2][4][4];
    #pragma unroll
    for (int i = 0; i < 2; i++)
        #pragma unroll
        for (int j = 0; j < 4; j++)
            #pragma unroll
            for (int k = 0; k < 4; k++) acc[i][j][k] = 0.f;

    const int m0 = blockIdx.y * 64, n0 = blockIdx.x * 64;
    gemm64_core(A, Bm, K, m0, n0, As, Bs, acc);

    const int lane = threadIdx.x & 31, warp = threadIdx.x >> 5;
    const int wm = (warp >> 1) * 32, wn = (warp & 1) * 32;
    #pragma unroll
    for (int mt = 0; mt < 2; ++mt) {
        const int r = m0 + wm + mt * 16 + (lane >> 2);
        #pragma unroll
        for (int nt = 0; nt < 4; ++nt) {
            const int cc = n0 + wn + nt * 8 + (lane & 3) * 2;
            float a00 = 0.f, a01 = 0.f;
            if (bias) { a00 = bias[cc]; a01 = bias[cc + 1]; }
            float a10 = a00, a11 = a01;
            if (addv) {
                a00 += addv[(size_t)(r & 255) * NG + cc];
                a01 += addv[(size_t)(r & 255) * NG + cc + 1];
                a10 += addv[(size_t)((r + 8) & 255) * NG + cc];
                a11 += addv[(size_t)((r + 8) & 255) * NG + cc + 1];
            }
            *(float2*)(C + (size_t)r * N + cc) =
                make_float2(acc[mt][nt][0] + a00, acc[mt][nt][1] + a01);
            *(float2*)(C + (size_t)(r + 8) * N + cc) =
                make_float2(acc[mt][nt][2] + a10, acc[mt][nt][3] + a11);
        }
    }
}

// ------------- fused logits GEMM (64x64) + per-block log-softmax partials ------
__global__ void __launch_bounds__(128)
k_logits(int t, const int* __restrict__ seqz) {
    __shared__ __align__(16) __nv_bfloat16 As[2][64][40];
    __shared__ __align__(16) __nv_bfloat16 Bs[2][64][40];
    __shared__ float redM[64][2];
    __shared__ float redS[64][2];
    __shared__ int   stgt[64];

    float acc[2][4][4];
    #pragma unroll
    for (int i = 0; i < 2; i++)
        #pragma unroll
        for (int j = 0; j < 4; j++)
            #pragma unroll
            for (int k = 0; k < 4; k++) acc[i][j][k] = 0.f;

    const int tid = threadIdx.x;
    const int m0 = blockIdx.y * 64, n0 = blockIdx.x * 64;
    if (tid < 64) stgt[tid] = seqz[(m0 + tid) * TT + t];

    gemm64_core(g_s, g_outWT, RNN, m0, n0, As, Bs, acc);

    const int lane = tid & 31, warp = tid >> 5;
    const int wm = (warp >> 1) * 32, wn = (warp & 1) * 32;
    const int w2 = warp & 1;

    // fold bias in once (cols shared across mt)
    #pragma unroll
    for (int nt = 0; nt < 4; ++nt) {
        const int c = n0 + wn + nt * 8 + (lane & 3) * 2;
        const float b0 = g_bias_out[c], b1 = g_bias_out[c + 1];
        #pragma unroll
        for (int mt = 0; mt < 2; ++mt) {
            acc[mt][nt][0] += b0; acc[mt][nt][1] += b1;
            acc[mt][nt][2] += b0; acc[mt][nt][3] += b1;
        }
    }

    // phase A: per-row max over block's 64 cols (+ target capture + padding mask)
    #pragma unroll
    for (int mt = 0; mt < 2; ++mt) {
        #pragma unroll
        for (int half = 0; half < 2; ++half) {
            const int rl = wm + mt * 16 + (lane >> 2) + half * 8;
            const int tgt = stgt[rl];
            float lmax = -1e30f;
            #pragma unroll
            for (int nt = 0; nt < 4; ++nt) {
                const int c = n0 + wn + nt * 8 + (lane & 3) * 2;
                float v0 = acc[mt][nt][half * 2 + 0];
                float v1 = acc[mt][nt][half * 2 + 1];
                if (c >= NL) v0 = -1e30f;
                else if (c == tgt) g_tgtval[m0 + rl] = v0;
                if (c + 1 >= NL) v1 = -1e30f;
                else if (c + 1 == tgt) g_tgtval[m0 + rl] = v1;
                acc[mt][nt][half * 2 + 0] = v0;   // keep masked value
                acc[mt][nt][half * 2 + 1] = v1;
                lmax = fmaxf(lmax, fmaxf(v0, v1));
            }
            lmax = fmaxf(lmax, __shfl_xor_sync(0xffffffffu, lmax, 1));
            lmax = fmaxf(lmax, __shfl_xor_sync(0xffffffffu, lmax, 2));
            if ((lane & 3) == 0) redM[rl][w2] = lmax;
        }
    }
    __syncthreads();

    // phase B: per-row sum of exp(v - rowmax)
    #pragma unroll
    for (int mt = 0; mt < 2; ++mt) {
        #pragma unroll
        for (int half = 0; half < 2; ++half) {
            const int rl = wm + mt * 16 + (lane >> 2) + half * 8;
            const float Mr = fmaxf(redM[rl][0], redM[rl][1]);
            float ls = 0.f;
            #pragma unroll
            for (int nt = 0; nt < 4; ++nt) {
                ls += __expf(acc[mt][nt][half * 2 + 0] - Mr);
                ls += __expf(acc[mt][nt][half * 2 + 1] - Mr);
            }
            ls += __shfl_xor_sync(0xffffffffu, ls, 1);
            ls += __shfl_xor_sync(0xffffffffu, ls, 2);
            if ((lane & 3) == 0) redS[rl][w2] = ls;
        }
    }
    __syncthreads();

    if (tid < 64) {
        float Mr = fmaxf(redM[tid][0], redM[tid][1]);
        float Sr = redS[tid][0] + redS[tid][1];
        g_part[blockIdx.x * BN + m0 + tid] = make_float2(Mr, Sr);
    }
}

// combine NPB partials for one b (thread-local, 4 independent chains)
__device__ __forceinline__ void final_rows(int t, const int* __restrict__ seqz,
                                           float* __restrict__ out) {
    const int b = threadIdx.x;   // 256 threads
    float M[4] = {-1e30f, -1e30f, -1e30f, -1e30f};
    float S[4] = {0.f, 0.f, 0.f, 0.f};
    for (int base = 0; base < NPB; base += 4) {
        #pragma unroll
        for (int q = 0; q < 4; ++q) {
            int nb = base + q;
            if (nb < NPB) {
                float2 p = g_part[nb * BN + b];
                if (p.x > M[q]) { S[q] = S[q] * __expf(M[q] - p.x) + p.y; M[q] = p.x; }
                else            { S[q] += p.y * __expf(p.x - M[q]); }
            }
        }
    }
    float Mf = fmaxf(fmaxf(M[0], M[1]), fmaxf(M[2], M[3]));
    float Sf = S[0] * __expf(M[0] - Mf) + S[1] * __expf(M[1] - Mf)
             + S[2] * __expf(M[2] - Mf) + S[3] * __expf(M[3] - Mf);
    float lse = Mf + logf(Sf);
    bool msk = (t == 0) || (seqz[b * TT + t - 1] != 0);
    out[t * BN + b] = msk ? (g_tgtval[b] - lse) : 0.f;
}

// ---------------- per-step cell (+ folded finalize of step t-1) ----------------
__global__ void k_cellfinal(int t, const int* __restrict__ seqz, float* __restrict__ out) {
    if (blockIdx.x == 512) {           // finalize previous step's log-softmax
        if (t > 0) final_rows(t - 1, seqz, out);
        return;
    }
    int i = blockIdx.x * 256 + threadIdx.x;
    int b = i >> 9, j = i & 511;
    const float* wg = g_wordgates + (size_t)(t * BN + b) * NG;  // includes vis+bias
    const float* hg = g_hgates   + (size_t)b * NG;
    float ig = wg[j]        + hg[j];
    float fg = wg[512 + j]  + hg[512 + j];
    float gg = wg[1024 + j] + hg[1024 + j];
    float og = wg[1536 + j] + hg[1536 + j];
    float gp = wg[2048 + j] + hg[2048 + j];
    float c  = g_c[i];
    float cn = sigf(fg) * c + sigf(ig) * tanhf(gg);
    float tc = tanhf(cn);
    g_c[i] = cn;
    g_h[i] = __float2bfloat16(sigf(og) * tc);
    g_s[i] = __float2bfloat16(sigf(gp) * tc);
}

__global__ void k_finlast(const int* __restrict__ seqz, float* __restrict__ out) {
    final_rows(TT - 1, seqz, out);
}

// ---------------- launch ----------------
extern "C" void kernel_launch(void* const* d_in, const int* in_sizes, int n_in,
                              void* d_out, int out_size) {
    (void)in_sizes; (void)n_in; (void)out_size;
    const float* vis    = (const float*)d_in[0];
    const int*   seqz   = (const int*)d_in[1];
    const float* emb    = (const float*)d_in[2];
    const float* W_ih   = (const float*)d_in[3];
    const float* W_hh   = (const float*)d_in[4];
    const float* b_lstm = (const float*)d_in[5];
    const float* v2gW   = (const float*)d_in[6];
    const float* v2gb   = (const float*)d_in[7];
    const float* w2gW   = (const float*)d_in[8];
    const float* h2gW   = (const float*)d_in[9];
    const float* outW   = (const float*)d_in[10];
    const float* outb   = (const float*)d_in[11];
    float* out = (float*)d_out;

    __nv_bfloat16 *pVisA, *pWvisT, *pWwT, *pWhhT, *pOutWT, *pWordsA, *pH;
    float *pBiasVis, *pVisG, *pWordG, *pHG;
    cudaGetSymbolAddress((void**)&pVisA,   g_visA);
    cudaGetSymbolAddress((void**)&pWvisT,  g_WvisT);
    cudaGetSymbolAddress((void**)&pWwT,    g_WwT);
    cudaGetSymbolAddress((void**)&pWhhT,   g_WhhT);
    cudaGetSymbolAddress((void**)&pOutWT,  g_outWT);
    cudaGetSymbolAddress((void**)&pWordsA, g_wordsA);
    cudaGetSymbolAddress((void**)&pH,      g_h);
    cudaGetSymbolAddress((void**)&pBiasVis, g_biasvis);
    cudaGetSymbolAddress((void**)&pVisG,   g_visgates);
    cudaGetSymbolAddress((void**)&pWordG,  g_wordgates);
    cudaGetSymbolAddress((void**)&pHG,     g_hgates);

    dim3 tb(32, 8);
    k_cvt_vis<<<(BN * VISD) / 256, 256>>>(vis);
    k_transpose_cvt<<<dim3(2048/32, 1024/32), tb>>>(W_ih, 2048, 1024, 2048, pWvisT, 1024, 2048);
    k_transpose_cvt<<<dim3(512/32, 1024/32),  tb>>>(v2gW, 512, 1024, 512, pWvisT + 2048*1024, 1024, 512);
    k_transpose_cvt<<<dim3(2048/32, 512/32),  tb>>>(W_ih + 1024*2048, 2048, 512, 2048, pWwT, 512, 2048);
    k_transpose_cvt<<<dim3(512/32, 512/32),   tb>>>(w2gW, 512, 512, 512, pWwT + 2048*512, 512, 512);
    k_transpose_cvt<<<dim3(2048/32, 512/32),  tb>>>(W_hh, 2048, 512, 2048, pWhhT, 512, 2048);
    k_transpose_cvt<<<dim3(512/32, 512/32),   tb>>>(h2gW, 512, 512, 512, pWhhT + 2048*512, 512, 512);
    k_transpose_cvt<<<dim3(NLP/32, 512/32),   tb>>>(outW, NL, 512, NL, pOutWT, 512, NLP);
    k_bias<<<(NLP + 255) / 256, 256>>>(b_lstm, v2gb, outb);
    k_wordsA<<<(MW * WORDD) / 256, 256>>>(emb, seqz);
    k_init<<<(BN * RNN) / 256, 256>>>();

    // loop-invariant GEMMs
    k_gemm<<<dim3(NG/64, BN/64), 128>>>(pVisA, pWvisT, pVisG, BN, NG, VISD, pBiasVis, nullptr);
    // wordgates = wordsA @ WwT^T + visgates[b]   (visgates already has biases)
    k_gemm<<<dim3(NG/64, MW/64), 128>>>(pWordsA, pWwT, pWordG, MW, NG, WORDD,
                                        nullptr, pVisG);

    for (int t = 0; t < TT; ++t) {
        k_gemm<<<dim3(NG/64, BN/64), 128>>>(pH, pWhhT, pHG, BN, NG, RNN, nullptr, nullptr);
        k_cellfinal<<<513, 256>>>(t, seqz, out);
        k_logits<<<dim3(NPB, BN/64), 128>>>(t, seqz);
    }
    k_finlast<<<1, 256>>>(seqz, out);
}

// round 5
// speedup vs baseline: 1.7725x; 1.7725x over previous
#include <cuda_runtime.h>
#include <cuda_bf16.h>
#include <math.h>
#include <stdint.h>

// Problem constants
#define BN    256
#define TT    64
#define VOC   10000
#define VISD  1024
#define WORDD 512
#define RNN   512
#define G4    2048
#define NG    2560          // 2048 lstm gates + 512 sentinel gate
#define NL    10001
#define NLP   10048         // padded to multiple of 64
#define MW    (TT*BN)       // 16384

// ---------------- device scratch ----------------
__device__ __nv_bfloat16 g_visA[BN*VISD];
__device__ __nv_bfloat16 g_WvisT[NG*VISD];
__device__ float         g_biasvis[NG];
__device__ float         g_visgates[BN*NG];
__device__ __nv_bfloat16 g_wordsA[MW*WORDD];
__device__ __nv_bfloat16 g_WwT[NG*WORDD];
__device__ float         g_wordgates[MW*NG];
__device__ __nv_bfloat16 g_WhhT[NG*RNN];
__device__ __nv_bfloat16 g_outWT[NLP*RNN];
__device__ float         g_bias_out[NLP];
__device__ float         g_hgates[BN*NG];
__device__ float         g_logits[BN*NLP];
__device__ float         g_c[BN*RNN];
__device__ __nv_bfloat16 g_h[BN*RNN];
__device__ __nv_bfloat16 g_s[BN*RNN];

// ---------------- helpers ----------------
__device__ __forceinline__ uint32_t s2u(const void* p) {
    return (uint32_t)__cvta_generic_to_shared(p);
}
__device__ __forceinline__ void ldsm4(uint32_t r[4], uint32_t addr) {
    asm volatile("ldmatrix.sync.aligned.m8n8.x4.shared.b16 {%0,%1,%2,%3}, [%4];"
                 : "=r"(r[0]), "=r"(r[1]), "=r"(r[2]), "=r"(r[3]) : "r"(addr));
}
__device__ __forceinline__ void mma16816(float c[4], const uint32_t a[4],
                                         uint32_t b0, uint32_t b1) {
    asm volatile(
        "mma.sync.aligned.m16n8k16.row.col.f32.bf16.bf16.f32 "
        "{%0,%1,%2,%3}, {%4,%5,%6,%7}, {%8,%9}, {%0,%1,%2,%3};"
        : "+f"(c[0]), "+f"(c[1]), "+f"(c[2]), "+f"(c[3])
        : "r"(a[0]), "r"(a[1]), "r"(a[2]), "r"(a[3]), "r"(b0), "r"(b1));
}
__device__ __forceinline__ void cpasync16(const void* smem, const void* g) {
    asm volatile("cp.async.cg.shared.global [%0], [%1], 16;\n"
                 :: "r"(s2u(smem)), "l"(g));
}
#define CPCOMMIT() asm volatile("cp.async.commit_group;\n" ::)
#define CPWAIT0()  asm volatile("cp.async.wait_group 0;\n" ::)

__device__ __forceinline__ float sigf(float x) { return 1.f / (1.f + expf(-x)); }

// ---------------- prep kernels ----------------
__global__ void k_cvt_vis(const float* __restrict__ vis) {
    int i = blockIdx.x * 256 + threadIdx.x;
    g_visA[i] = __float2bfloat16(vis[i]);
}

__global__ void k_transpose_cvt(const float* __restrict__ src, int sld, int K, int N,
                                __nv_bfloat16* __restrict__ dst, int dld, int Ndst) {
    __shared__ float tile[32][33];
    int nb = blockIdx.x * 32, kb = blockIdx.y * 32;
    int tx = threadIdx.x, ty = threadIdx.y;
    #pragma unroll
    for (int i = ty; i < 32; i += 8) {
        int k = kb + i, n = nb + tx;
        tile[i][tx] = (k < K && n < N) ? src[(size_t)k * sld + n] : 0.f;
    }
    __syncthreads();
    #pragma unroll
    for (int i = ty; i < 32; i += 8) {
        int n = nb + i, k = kb + tx;
        if (n < Ndst) dst[(size_t)n * dld + k] = __float2bfloat16(tile[tx][i]);
    }
}

__global__ void k_bias(const float* __restrict__ bl, const float* __restrict__ vb,
                       const float* __restrict__ ob) {
    int i = blockIdx.x * 256 + threadIdx.x;
    if (i < NG)  g_biasvis[i] = (i < G4) ? bl[i] : vb[i - G4];
    if (i < NLP) g_bias_out[i] = (i < NL) ? ob[i] : 0.f;
}

__global__ void k_wordsA(const float* __restrict__ emb, const int* __restrict__ seqz) {
    int idx = blockIdx.x * 256 + threadIdx.x;
    int r = idx >> 9, k = idx & 511;
    int t = r >> 8, b = r & 255;
    int widx = (t == 0) ? (VOC + 1) : seqz[b * TT + (t - 1)];
    g_wordsA[idx] = __float2bfloat16(emb[(size_t)widx * WORDD + k]);
}

__global__ void k_init() {
    int i = blockIdx.x * 256 + threadIdx.x;
    g_h[i] = __float2bfloat16(0.f);
    g_c[i] = 0.f;
}

// ---------------- 64x64 MMA GEMM with cp.async 2-stage pipeline ----------------
__global__ void __launch_bounds__(128)
k_gemm(const __nv_bfloat16* __restrict__ A, const __nv_bfloat16* __restrict__ Bm,
       float* __restrict__ C, int M, int N, int K, const float* __restrict__ bias) {
    __shared__ __align__(16) __nv_bfloat16 As[2][64][40];
    __shared__ __align__(16) __nv_bfloat16 Bs[2][64][40];

    const int tid  = threadIdx.x;
    const int lane = tid & 31;
    const int warp = tid >> 5;
    const int m0 = blockIdx.y * 64;
    const int n0 = blockIdx.x * 64;
    const int wm = (warp >> 1) * 32;
    const int wn = (warp & 1) * 32;

    float acc[2][4][4];
    #pragma unroll
    for (int i = 0; i < 2; i++)
        #pragma unroll
        for (int j = 0; j < 4; j++)
            #pragma unroll
            for (int k = 0; k < 4; k++) acc[i][j][k] = 0.f;

    const int lr = tid >> 2;          // 0..31
    const int lc = (tid & 3) * 8;     // 0,8,16,24

    const __nv_bfloat16* Ag0 = A  + (size_t)(m0 + lr)      * K + lc;
    const __nv_bfloat16* Ag1 = A  + (size_t)(m0 + lr + 32) * K + lc;
    const __nv_bfloat16* Bg0 = Bm + (size_t)(n0 + lr)      * K + lc;
    const __nv_bfloat16* Bg1 = Bm + (size_t)(n0 + lr + 32) * K + lc;

    // prologue: stage 0
    cpasync16(&As[0][lr][lc],      Ag0);
    cpasync16(&As[0][lr + 32][lc], Ag1);
    cpasync16(&Bs[0][lr][lc],      Bg0);
    cpasync16(&Bs[0][lr + 32][lc], Bg1);
    CPCOMMIT();

    const int KT = K >> 5;
    for (int kt = 0; kt < KT; ++kt) {
        CPWAIT0();
        __syncthreads();
        if (kt + 1 < KT) {
            const int s = (kt + 1) & 1;
            const int kb = (kt + 1) << 5;
            cpasync16(&As[s][lr][lc],      Ag0 + kb);
            cpasync16(&As[s][lr + 32][lc], Ag1 + kb);
            cpasync16(&Bs[s][lr][lc],      Bg0 + kb);
            cpasync16(&Bs[s][lr + 32][lc], Bg1 + kb);
            CPCOMMIT();
        }
        const int cur = kt & 1;
        #pragma unroll
        for (int ks = 0; ks < 2; ++ks) {
            uint32_t af[2][4], bfq[2][4];
            #pragma unroll
            for (int mt = 0; mt < 2; ++mt)
                ldsm4(af[mt], s2u(&As[cur][wm + mt * 16 + (lane & 15)]
                                          [ks * 16 + (lane >> 4) * 8]));
            #pragma unroll
            for (int np = 0; np < 2; ++np)
                ldsm4(bfq[np], s2u(&Bs[cur][wn + np * 16 + (lane & 7) + ((lane >> 4) & 1) * 8]
                                           [ks * 16 + ((lane >> 3) & 1) * 8]));
            #pragma unroll
            for (int mt = 0; mt < 2; ++mt)
                #pragma unroll
                for (int nt = 0; nt < 4; ++nt)
                    mma16816(acc[mt][nt], af[mt],
                             bfq[nt >> 1][(nt & 1) * 2], bfq[nt >> 1][(nt & 1) * 2 + 1]);
        }
    }

    #pragma unroll
    for (int mt = 0; mt < 2; ++mt) {
        const int r = m0 + wm + mt * 16 + (lane >> 2);
        #pragma unroll
        for (int nt = 0; nt < 4; ++nt) {
            const int cc = n0 + wn + nt * 8 + (lane & 3) * 2;
            float b0v = 0.f, b1v = 0.f;
            if (bias) { b0v = bias[cc]; b1v = bias[cc + 1]; }
            float2 v0 = make_float2(acc[mt][nt][0] + b0v, acc[mt][nt][1] + b1v);
            float2 v1 = make_float2(acc[mt][nt][2] + b0v, acc[mt][nt][3] + b1v);
            *(float2*)(C + (size_t)r * N + cc)       = v0;
            *(float2*)(C + (size_t)(r + 8) * N + cc) = v1;
        }
    }
}

// ---------------- 128x128 cp.async GEMM (big precompute only) ----------------
__global__ void __launch_bounds__(256)
k_gemm128(const __nv_bfloat16* __restrict__ A, const __nv_bfloat16* __restrict__ Bm,
          float* __restrict__ C, int N, int K) {
    __shared__ __align__(16) __nv_bfloat16 As[2][128][40];
    __shared__ __align__(16) __nv_bfloat16 Bs[2][128][40];
    float acc[4][4][4];
    #pragma unroll
    for (int a = 0; a < 4; a++)
        #pragma unroll
        for (int b = 0; b < 4; b++)
            #pragma unroll
            for (int c = 0; c < 4; c++) acc[a][b][c] = 0.f;

    const int tid  = threadIdx.x;
    const int lane = tid & 31;
    const int warp = tid >> 5;
    const int m0 = blockIdx.y * 128, n0 = blockIdx.x * 128;
    const int wmoff = (warp >> 2) * 64;
    const int wnoff = (warp & 3) * 32;
    const int lr = tid >> 2;          // 0..63
    const int lc = (tid & 3) * 8;

    const __nv_bfloat16* Ab = A + (size_t)m0 * K;
    const __nv_bfloat16* Bb = Bm + (size_t)n0 * K;

    cpasync16(&As[0][lr][lc],      Ab + (size_t)lr * K + lc);
    cpasync16(&As[0][lr + 64][lc], Ab + (size_t)(lr + 64) * K + lc);
    cpasync16(&Bs[0][lr][lc],      Bb + (size_t)lr * K + lc);
    cpasync16(&Bs[0][lr + 64][lc], Bb + (size_t)(lr + 64) * K + lc);
    CPCOMMIT();

    const int KT = K >> 5;
    for (int kt = 0; kt < KT; ++kt) {
        CPWAIT0();
        __syncthreads();
        if (kt + 1 < KT) {
            const int s = (kt + 1) & 1;
            const int kb = (kt + 1) << 5;
            cpasync16(&As[s][lr][lc],      Ab + (size_t)lr * K + kb + lc);
            cpasync16(&As[s][lr + 64][lc], Ab + (size_t)(lr + 64) * K + kb + lc);
            cpasync16(&Bs[s][lr][lc],      Bb + (size_t)lr * K + kb + lc);
            cpasync16(&Bs[s][lr + 64][lc], Bb + (size_t)(lr + 64) * K + kb + lc);
            CPCOMMIT();
        }
        const int s = kt & 1;
        #pragma unroll
        for (int ks = 0; ks < 2; ++ks) {
            uint32_t af[4][4], bfq[2][4];
            #pragma unroll
            for (int mt = 0; mt < 4; ++mt)
                ldsm4(af[mt], s2u(&As[s][wmoff + mt * 16 + (lane & 15)]
                                        [ks * 16 + (lane >> 4) * 8]));
            #pragma unroll
            for (int np = 0; np < 2; ++np)
                ldsm4(bfq[np], s2u(&Bs[s][wnoff + np * 16 + (lane & 7) + ((lane >> 4) & 1) * 8]
                                         [ks * 16 + ((lane >> 3) & 1) * 8]));
            #pragma unroll
            for (int mt = 0; mt < 4; ++mt)
                #pragma unroll
                for (int nt = 0; nt < 4; ++nt)
                    mma16816(acc[mt][nt], af[mt],
                             bfq[nt >> 1][(nt & 1) * 2], bfq[nt >> 1][(nt & 1) * 2 + 1]);
        }
    }

    #pragma unroll
    for (int mt = 0; mt < 4; ++mt) {
        const int r = m0 + wmoff + mt * 16 + (lane >> 2);
        #pragma unroll
        for (int nt = 0; nt < 4; ++nt) {
            const int cc = n0 + wnoff + nt * 8 + (lane & 3) * 2;
            *(float2*)(C + (size_t)r * N + cc) =
                make_float2(acc[mt][nt][0], acc[mt][nt][1]);
            *(float2*)(C + (size_t)(r + 8) * N + cc) =
                make_float2(acc[mt][nt][2], acc[mt][nt][3]);
        }
    }
}

// ---------------- per-step pointwise LSTM cell + sentinel gate ----------------
__global__ void k_cell(int t) {
    int i = blockIdx.x * 256 + threadIdx.x;          // exactly BN*RNN threads
    int b = i >> 9, j = i & 511;
    const float* wg = g_wordgates + (size_t)(t * BN + b) * NG;
    const float* hg = g_hgates   + (size_t)b * NG;
    const float* vg = g_visgates + (size_t)b * NG;
    float ig = wg[j]        + hg[j]        + vg[j];
    float fg = wg[512 + j]  + hg[512 + j]  + vg[512 + j];
    float gg = wg[1024 + j] + hg[1024 + j] + vg[1024 + j];
    float og = wg[1536 + j] + hg[1536 + j] + vg[1536 + j];
    float gp = wg[2048 + j] + hg[2048 + j] + vg[2048 + j];
    float c  = g_c[i];
    float cn = sigf(fg) * c + sigf(ig) * tanhf(gg);
    float tc = tanhf(cn);
    g_c[i] = cn;
    g_h[i] = __float2bfloat16(sigf(og) * tc);
    g_s[i] = __float2bfloat16(sigf(gp) * tc);
}

// ---------------- per-row logsumexp + target gather ----------------
__global__ void k_output(int t, const int* __restrict__ seqz, float* __restrict__ out) {
    int b = blockIdx.x;
    int tid = threadIdx.x;
    const float* row = g_logits + (size_t)b * NLP;
    __shared__ float red[8];

    float m = -1e30f;
    for (int j = tid; j < NL; j += 256) m = fmaxf(m, row[j]);
    #pragma unroll
    for (int o = 16; o > 0; o >>= 1) m = fmaxf(m, __shfl_xor_sync(0xffffffffu, m, o));
    if ((tid & 31) == 0) red[tid >> 5] = m;
    __syncthreads();
    float M = -1e30f;
    #pragma unroll
    for (int i = 0; i < 8; ++i) M = fmaxf(M, red[i]);
    __syncthreads();

    float s = 0.f;
    for (int j = tid; j < NL; j += 256) s += expf(row[j] - M);
    #pragma unroll
    for (int o = 16; o > 0; o >>= 1) s += __shfl_xor_sync(0xffffffffu, s, o);
    if ((tid & 31) == 0) red[tid >> 5] = s;
    __syncthreads();

    if (tid == 0) {
        float tot = 0.f;
        #pragma unroll
        for (int i = 0; i < 8; ++i) tot += red[i];
        float lse = M + logf(tot);
        int tgt = seqz[b * TT + t];
        bool msk = (t == 0) || (seqz[b * TT + t - 1] != 0);
        out[t * BN + b] = msk ? (row[tgt] - lse) : 0.f;
    }
}

// ---------------- launch ----------------
extern "C" void kernel_launch(void* const* d_in, const int* in_sizes, int n_in,
                              void* d_out, int out_size) {
    (void)in_sizes; (void)n_in; (void)out_size;
    const float* vis    = (const float*)d_in[0];
    const int*   seqz   = (const int*)d_in[1];
    const float* emb    = (const float*)d_in[2];
    const float* W_ih   = (const float*)d_in[3];
    const float* W_hh   = (const float*)d_in[4];
    const float* b_lstm = (const float*)d_in[5];
    const float* v2gW   = (const float*)d_in[6];
    const float* v2gb   = (const float*)d_in[7];
    const float* w2gW   = (const float*)d_in[8];
    const float* h2gW   = (const float*)d_in[9];
    const float* outW   = (const float*)d_in[10];
    const float* outb   = (const float*)d_in[11];
    float* out = (float*)d_out;

    __nv_bfloat16 *pVisA, *pWvisT, *pWwT, *pWhhT, *pOutWT, *pWordsA, *pH, *pS;
    float *pBiasVis, *pBiasOut, *pVisG, *pWordG, *pHG, *pLogits;
    cudaGetSymbolAddress((void**)&pVisA,   g_visA);
    cudaGetSymbolAddress((void**)&pWvisT,  g_WvisT);
    cudaGetSymbolAddress((void**)&pWwT,    g_WwT);
    cudaGetSymbolAddress((void**)&pWhhT,   g_WhhT);
    cudaGetSymbolAddress((void**)&pOutWT,  g_outWT);
    cudaGetSymbolAddress((void**)&pWordsA, g_wordsA);
    cudaGetSymbolAddress((void**)&pH,      g_h);
    cudaGetSymbolAddress((void**)&pS,      g_s);
    cudaGetSymbolAddress((void**)&pBiasVis, g_biasvis);
    cudaGetSymbolAddress((void**)&pBiasOut, g_bias_out);
    cudaGetSymbolAddress((void**)&pVisG,   g_visgates);
    cudaGetSymbolAddress((void**)&pWordG,  g_wordgates);
    cudaGetSymbolAddress((void**)&pHG,     g_hgates);
    cudaGetSymbolAddress((void**)&pLogits, g_logits);

    dim3 tb(32, 8);
    k_cvt_vis<<<(BN * VISD) / 256, 256>>>(vis);
    k_transpose_cvt<<<dim3(2048/32, 1024/32), tb>>>(W_ih, 2048, 1024, 2048, pWvisT, 1024, 2048);
    k_transpose_cvt<<<dim3(512/32, 1024/32),  tb>>>(v2gW, 512, 1024, 512, pWvisT + 2048*1024, 1024, 512);
    k_transpose_cvt<<<dim3(2048/32, 512/32),  tb>>>(W_ih + 1024*2048, 2048, 512, 2048, pWwT, 512, 2048);
    k_transpose_cvt<<<dim3(512/32, 512/32),   tb>>>(w2gW, 512, 512, 512, pWwT + 2048*512, 512, 512);
    k_transpose_cvt<<<dim3(2048/32, 512/32),  tb>>>(W_hh, 2048, 512, 2048, pWhhT, 512, 2048);
    k_transpose_cvt<<<dim3(512/32, 512/32),   tb>>>(h2gW, 512, 512, 512, pWhhT + 2048*512, 512, 512);
    k_transpose_cvt<<<dim3(NLP/32, 512/32),   tb>>>(outW, NL, 512, NL, pOutWT, 512, NLP);
    k_bias<<<(NLP + 255) / 256, 256>>>(b_lstm, v2gb, outb);
    k_wordsA<<<(MW * WORDD) / 256, 256>>>(emb, seqz);
    k_init<<<(BN * RNN) / 256, 256>>>();

    // loop-invariant GEMMs
    k_gemm<<<dim3(NG/64, BN/64), 128>>>(pVisA, pWvisT, pVisG, BN, NG, VISD, pBiasVis);
    k_gemm128<<<dim3(NG/128, MW/128), 256>>>(pWordsA, pWwT, pWordG, NG, WORDD);

    for (int t = 0; t < TT; ++t) {
        k_gemm<<<dim3(NG/64, BN/64), 128>>>(pH, pWhhT, pHG, BN, NG, RNN, nullptr);
        k_cell<<<(BN * RNN) / 256, 256>>>(t);
        k_gemm<<<dim3(NLP/64, BN/64), 128>>>(pS, pOutWT, pLogits, BN, NLP, RNN, pBiasOut);
        k_output<<<BN, 256>>>(t, seqz, out);
    }
}